// round 1
// baseline (speedup 1.0000x reference)
#include <cuda_runtime.h>

#define N_NODES  50000
#define N_EDGES  800000
#define N_GRAPHS 128
#define D        128

// ---------------- scratch (device globals; no allocation allowed) ----------
__device__ float g_hw[N_NODES * D];     // GEMM output, scaled by dinv[row]
__device__ float g_h [N_NODES * D];     // layer activations (ping-pong safe)
__device__ int   g_degi[N_NODES];       // in-degree (without self loop)
__device__ float g_dinv[N_NODES];       // rsqrt(deg+1)
__device__ int   g_rowptr[N_NODES + 1]; // CSR by target node
__device__ int   g_cursor[N_NODES];
__device__ int   g_csr[N_EDGES];        // source node per CSR slot
__device__ float g_gs[N_GRAPHS * D];    // per-graph feature sums
__device__ float g_gcnt[N_GRAPHS];      // per-graph node counts

// ---------------- setup kernels --------------------------------------------
__global__ void zero_kernel() {
    int i = blockIdx.x * blockDim.x + threadIdx.x;
    if (i < N_NODES) g_degi[i] = 0;
    if (i < N_GRAPHS * D) g_gs[i] = 0.f;
    if (i < N_GRAPHS) g_gcnt[i] = 0.f;
}

__global__ void hist_kernel(const int* __restrict__ col) {
    int e = blockIdx.x * blockDim.x + threadIdx.x;
    if (e < N_EDGES) atomicAdd(&g_degi[col[e]], 1);
}

__global__ void dinv_kernel() {
    int i = blockIdx.x * blockDim.x + threadIdx.x;
    if (i < N_NODES) g_dinv[i] = rsqrtf((float)(g_degi[i] + 1));
}

// single-block scan over 50000 ints -> rowptr (exclusive) and cursor copy
__global__ void scan_kernel() {
    __shared__ int sh[1024];
    int tid = threadIdx.x;
    if (tid == 0) g_rowptr[0] = 0;
    int run = 0;
    for (int base = 0; base < N_NODES; base += 1024) {
        int idx = base + tid;
        int v = (idx < N_NODES) ? g_degi[idx] : 0;
        sh[tid] = v;
        __syncthreads();
        #pragma unroll
        for (int s = 1; s < 1024; s <<= 1) {
            int t = (tid >= s) ? sh[tid - s] : 0;
            __syncthreads();
            sh[tid] += t;
            __syncthreads();
        }
        int incl = sh[tid];
        if (idx < N_NODES) {
            g_rowptr[idx + 1] = run + incl;      // exclusive prefix end
            g_cursor[idx]     = run + incl - v;  // exclusive prefix start
        }
        run += sh[1023];
        __syncthreads();
    }
}

__global__ void scatter_kernel(const int* __restrict__ row,
                               const int* __restrict__ col) {
    int e = blockIdx.x * blockDim.x + threadIdx.x;
    if (e < N_EDGES) {
        int c = col[e];
        int p = atomicAdd(&g_cursor[c], 1);
        g_csr[p] = row[e];
    }
}

// ---------------- fused GEMM: out[n] = dinv[n] * (A[n] @ W) ----------------
// BM=128, BN=128, K=128 fully in smem. 256 threads, each computes 8x8.
__global__ void gemm_scale_kernel(const float* __restrict__ A,
                                  const float* __restrict__ W,
                                  float* __restrict__ out, int n) {
    extern __shared__ float smem[];
    float* As = smem;            // [128][128] row-major
    float* Ws = smem + D * D;    // [128][128] row-major: Ws[k][c]
    int tid = threadIdx.x;
    int row0 = blockIdx.x * 128;

    const float4* W4 = (const float4*)W;
    float4* Ws4 = (float4*)Ws;
    #pragma unroll 4
    for (int i = tid; i < D * D / 4; i += 256) Ws4[i] = W4[i];

    float4* As4 = (float4*)As;
    const float4* A4 = (const float4*)A;
    #pragma unroll 4
    for (int i = tid; i < D * D / 4; i += 256) {
        int m = i >> 5;          // 0..127
        int gm = row0 + m;
        float4 v = make_float4(0.f, 0.f, 0.f, 0.f);
        if (gm < n) v = A4[gm * 32 + (i & 31)];
        As4[i] = v;
    }
    __syncthreads();

    int tx = tid & 15;           // 16 col groups of 8
    int ty = tid >> 4;           // 16 row groups of 8
    float acc[8][8];
    #pragma unroll
    for (int i = 0; i < 8; i++)
        #pragma unroll
        for (int j = 0; j < 8; j++) acc[i][j] = 0.f;

    #pragma unroll 4
    for (int k = 0; k < D; ++k) {
        float a[8];
        #pragma unroll
        for (int i = 0; i < 8; i++) a[i] = As[(ty * 8 + i) * D + k];
        const float4* wrow = (const float4*)(Ws + k * D + tx * 8);
        float4 b0 = wrow[0];
        float4 b1 = wrow[1];
        float b[8] = {b0.x, b0.y, b0.z, b0.w, b1.x, b1.y, b1.z, b1.w};
        #pragma unroll
        for (int i = 0; i < 8; i++)
            #pragma unroll
            for (int j = 0; j < 8; j++)
                acc[i][j] = fmaf(a[i], b[j], acc[i][j]);
    }

    #pragma unroll
    for (int i = 0; i < 8; i++) {
        int gm = row0 + ty * 8 + i;
        if (gm < n) {
            float dv = g_dinv[gm];
            float4 r0, r1;
            r0.x = acc[i][0] * dv; r0.y = acc[i][1] * dv;
            r0.z = acc[i][2] * dv; r0.w = acc[i][3] * dv;
            r1.x = acc[i][4] * dv; r1.y = acc[i][5] * dv;
            r1.z = acc[i][6] * dv; r1.w = acc[i][7] * dv;
            float4* orow = (float4*)(out + gm * D + tx * 8);
            orow[0] = r0;
            orow[1] = r1;
        }
    }
}

// ---------------- aggregation: warp per node, pure gather ------------------
__global__ void agg_kernel(const float4* __restrict__ hw,
                           const float* __restrict__ bias,
                           float4* __restrict__ out, int relu) {
    int gt = blockIdx.x * blockDim.x + threadIdx.x;
    int v = gt >> 5;
    int lane = gt & 31;
    if (v >= N_NODES) return;

    float4 acc = hw[v * 32 + lane];            // self loop term
    int s = g_rowptr[v], e = g_rowptr[v + 1];
    int i = s;
    for (; i + 2 <= e; i += 2) {
        int u0 = g_csr[i];
        int u1 = g_csr[i + 1];
        float4 t0 = hw[u0 * 32 + lane];
        float4 t1 = hw[u1 * 32 + lane];
        acc.x += t0.x + t1.x; acc.y += t0.y + t1.y;
        acc.z += t0.z + t1.z; acc.w += t0.w + t1.w;
    }
    if (i < e) {
        int u = g_csr[i];
        float4 t = hw[u * 32 + lane];
        acc.x += t.x; acc.y += t.y; acc.z += t.z; acc.w += t.w;
    }
    float dv = g_dinv[v];
    float4 b = ((const float4*)bias)[lane];
    float4 r;
    r.x = fmaf(dv, acc.x, b.x); r.y = fmaf(dv, acc.y, b.y);
    r.z = fmaf(dv, acc.z, b.z); r.w = fmaf(dv, acc.w, b.w);
    if (relu) {
        r.x = fmaxf(r.x, 0.f); r.y = fmaxf(r.y, 0.f);
        r.z = fmaxf(r.z, 0.f); r.w = fmaxf(r.w, 0.f);
    }
    out[v * 32 + lane] = r;
}

// layer 3: aggregate and pool directly (no h3 store)
__global__ void agg_pool_kernel(const float4* __restrict__ hw,
                                const float* __restrict__ bias,
                                const int* __restrict__ batch) {
    int gt = blockIdx.x * blockDim.x + threadIdx.x;
    int v = gt >> 5;
    int lane = gt & 31;
    if (v >= N_NODES) return;

    float4 acc = hw[v * 32 + lane];
    int s = g_rowptr[v], e = g_rowptr[v + 1];
    int i = s;
    for (; i + 2 <= e; i += 2) {
        int u0 = g_csr[i];
        int u1 = g_csr[i + 1];
        float4 t0 = hw[u0 * 32 + lane];
        float4 t1 = hw[u1 * 32 + lane];
        acc.x += t0.x + t1.x; acc.y += t0.y + t1.y;
        acc.z += t0.z + t1.z; acc.w += t0.w + t1.w;
    }
    if (i < e) {
        int u = g_csr[i];
        float4 t = hw[u * 32 + lane];
        acc.x += t.x; acc.y += t.y; acc.z += t.z; acc.w += t.w;
    }
    float dv = g_dinv[v];
    float4 b = ((const float4*)bias)[lane];
    float4 r;
    r.x = fmaf(dv, acc.x, b.x); r.y = fmaf(dv, acc.y, b.y);
    r.z = fmaf(dv, acc.z, b.z); r.w = fmaf(dv, acc.w, b.w);

    int g = batch[v];
    float* base = &g_gs[g * D + lane * 4];
    atomicAdd(base + 0, r.x);
    atomicAdd(base + 1, r.y);
    atomicAdd(base + 2, r.z);
    atomicAdd(base + 3, r.w);
}

__global__ void count_kernel(const int* __restrict__ batch) {
    int i = blockIdx.x * blockDim.x + threadIdx.x;
    if (i < N_NODES) atomicAdd(&g_gcnt[batch[i]], 1.0f);
}

// pooled @ Wlin + blin -> out[128][3]
__global__ void final_kernel(const float* __restrict__ Wlin,
                             const float* __restrict__ blin,
                             float* __restrict__ out) {
    __shared__ float Ws[D * 3];
    int t = threadIdx.x;          // 128 threads, one graph each
    for (int i = t; i < D * 3; i += 128) Ws[i] = Wlin[i];
    __syncthreads();
    int g = t;
    float inv = 1.0f / fmaxf(g_gcnt[g], 1.0f);
    float o0 = blin[0], o1 = blin[1], o2 = blin[2];
    #pragma unroll 4
    for (int c = 0; c < D; ++c) {
        float p = g_gs[g * D + c] * inv;
        o0 = fmaf(p, Ws[c * 3 + 0], o0);
        o1 = fmaf(p, Ws[c * 3 + 1], o1);
        o2 = fmaf(p, Ws[c * 3 + 2], o2);
    }
    out[g * 3 + 0] = o0;
    out[g * 3 + 1] = o1;
    out[g * 3 + 2] = o2;
}

// ---------------- launch ----------------------------------------------------
extern "C" void kernel_launch(void* const* d_in, const int* in_sizes, int n_in,
                              void* d_out, int out_size) {
    const float* x     = (const float*)d_in[0];
    const int*   ei    = (const int*)d_in[1];
    const int*   batch = (const int*)d_in[2];
    const float* W1 = (const float*)d_in[3];
    const float* b1 = (const float*)d_in[4];
    const float* W2 = (const float*)d_in[5];
    const float* b2 = (const float*)d_in[6];
    const float* W3 = (const float*)d_in[7];
    const float* b3 = (const float*)d_in[8];
    const float* Wlin = (const float*)d_in[9];
    const float* blin = (const float*)d_in[10];
    float* out = (float*)d_out;

    const int* row = ei;             // edge_index[0] = sources
    const int* col = ei + N_EDGES;   // edge_index[1] = targets

    const size_t gemm_smem = 2 * D * D * sizeof(float); // 128 KB
    cudaFuncSetAttribute(gemm_scale_kernel,
                         cudaFuncAttributeMaxDynamicSharedMemorySize,
                         (int)gemm_smem);

    float *hw_p = nullptr, *h_p = nullptr;
    cudaGetSymbolAddress((void**)&hw_p, g_hw);
    cudaGetSymbolAddress((void**)&h_p, g_h);

    const int nodeBlocks = (N_NODES + 255) / 256;
    const int edgeBlocks = (N_EDGES + 255) / 256;
    const int gemmGrid   = (N_NODES + 127) / 128;
    const int aggBlocks  = (N_NODES * 32 + 255) / 256;

    zero_kernel<<<nodeBlocks, 256>>>();
    hist_kernel<<<edgeBlocks, 256>>>(col);
    dinv_kernel<<<nodeBlocks, 256>>>();
    scan_kernel<<<1, 1024>>>();
    scatter_kernel<<<edgeBlocks, 256>>>(row, col);

    // layer 1
    gemm_scale_kernel<<<gemmGrid, 256, gemm_smem>>>(x, W1, hw_p, N_NODES);
    agg_kernel<<<aggBlocks, 256>>>((const float4*)hw_p, b1, (float4*)h_p, 1);
    // layer 2
    gemm_scale_kernel<<<gemmGrid, 256, gemm_smem>>>(h_p, W2, hw_p, N_NODES);
    agg_kernel<<<aggBlocks, 256>>>((const float4*)hw_p, b2, (float4*)h_p, 1);
    // layer 3 (fused pooling)
    gemm_scale_kernel<<<gemmGrid, 256, gemm_smem>>>(h_p, W3, hw_p, N_NODES);
    agg_pool_kernel<<<aggBlocks, 256>>>((const float4*)hw_p, b3, batch);

    count_kernel<<<nodeBlocks, 256>>>(batch);
    final_kernel<<<1, 128>>>(Wlin, blin, out);
}

// round 2
// speedup vs baseline: 1.0881x; 1.0881x over previous
#include <cuda_runtime.h>

#define N_NODES  50000
#define N_EDGES  800000
#define N_GRAPHS 128
#define D        128
#define SCAN_BLKS ((N_NODES + 1023) / 1024)   // 49

typedef unsigned long long u64;

// ---------------- scratch (device globals; no allocation allowed) ----------
__device__ float g_hw[N_NODES * D];     // GEMM output, scaled by dinv[row]
__device__ float g_h [N_NODES * D];     // layer activations
__device__ int   g_degi[N_NODES];       // in-degree (without self loop)
__device__ float g_dinv[N_NODES];       // rsqrt(deg+1)
__device__ int   g_scan[N_NODES];       // per-block inclusive scan
__device__ int   g_bsum[SCAN_BLKS];     // per-block totals
__device__ int   g_boff[SCAN_BLKS];     // exclusive offsets of block totals
__device__ int   g_rowptr[N_NODES + 1]; // CSR by target node
__device__ int   g_cursor[N_NODES];
__device__ int   g_csr[N_EDGES];        // source node per CSR slot
__device__ float g_gs[N_GRAPHS * D];    // per-graph feature sums
__device__ float g_gcnt[N_GRAPHS];      // per-graph node counts

// ---------------- f32x2 helpers ---------------------------------------------
__device__ __forceinline__ u64 ffma2(u64 a, u64 b, u64 c) {
    u64 d;
    asm("fma.rn.f32x2 %0, %1, %2, %3;" : "=l"(d) : "l"(a), "l"(b), "l"(c));
    return d;
}
__device__ __forceinline__ u64 fmul2(u64 a, u64 b) {
    u64 d;
    asm("mul.rn.f32x2 %0, %1, %2;" : "=l"(d) : "l"(a), "l"(b));
    return d;
}
__device__ __forceinline__ u64 dup2(float x) {
    u64 d;
    asm("mov.b64 %0, {%1, %1};" : "=l"(d) : "f"(x));
    return d;
}

// ---------------- setup kernels --------------------------------------------
__global__ void zero_kernel() {
    int i = blockIdx.x * blockDim.x + threadIdx.x;
    if (i < N_NODES) g_degi[i] = 0;
    if (i < N_GRAPHS * D) g_gs[i] = 0.f;
    if (i < N_GRAPHS) g_gcnt[i] = 0.f;
}

__global__ void hist_kernel(const int* __restrict__ col) {
    int e = blockIdx.x * blockDim.x + threadIdx.x;
    if (e < N_EDGES) atomicAdd(&g_degi[col[e]], 1);
}

// phase 1: per-block shuffle scan (1024 threads), also compute dinv
__global__ void scan_part_kernel() {
    __shared__ int wsum[32];
    int tid  = threadIdx.x;
    int lane = tid & 31;
    int wid  = tid >> 5;
    int idx  = blockIdx.x * 1024 + tid;
    int v = (idx < N_NODES) ? g_degi[idx] : 0;
    if (idx < N_NODES) g_dinv[idx] = rsqrtf((float)(v + 1));

    int x = v;
    #pragma unroll
    for (int s = 1; s < 32; s <<= 1) {
        int t = __shfl_up_sync(0xffffffffu, x, s);
        if (lane >= s) x += t;
    }
    if (lane == 31) wsum[wid] = x;
    __syncthreads();
    if (wid == 0) {
        int y = wsum[lane];
        #pragma unroll
        for (int s = 1; s < 32; s <<= 1) {
            int t = __shfl_up_sync(0xffffffffu, y, s);
            if (lane >= s) y += t;
        }
        wsum[lane] = y;
    }
    __syncthreads();
    int incl = x + (wid ? wsum[wid - 1] : 0);
    if (idx < N_NODES) g_scan[idx] = incl;
    if (tid == 1023) g_bsum[blockIdx.x] = incl;
}

// phase 2: scan 49 block totals (trivial)
__global__ void scan_bsum_kernel() {
    int run = 0;
    for (int i = 0; i < SCAN_BLKS; ++i) {
        g_boff[i] = run;
        run += g_bsum[i];
    }
}

// phase 3: finalize rowptr + cursor
__global__ void scan_final_kernel() {
    int idx = blockIdx.x * blockDim.x + threadIdx.x;
    if (idx == 0) g_rowptr[0] = 0;
    if (idx < N_NODES) {
        int incl = g_scan[idx] + g_boff[idx >> 10];
        g_rowptr[idx + 1] = incl;
        g_cursor[idx]     = incl - g_degi[idx];
    }
}

__global__ void scatter_kernel(const int* __restrict__ row,
                               const int* __restrict__ col) {
    int e = blockIdx.x * blockDim.x + threadIdx.x;
    if (e < N_EDGES) {
        int c = col[e];
        int p = atomicAdd(&g_cursor[c], 1);
        g_csr[p] = row[e];
    }
}

// ---------------- fused GEMM: out[n] = dinv[n] * (A[n] @ W) ----------------
// BM=128, BN=128, K=128 fully in smem. 256 threads, each computes 8x8 via
// packed f32x2 FMAs (accumulators held as 32 packed 64-bit pairs).
__global__ void gemm_scale_kernel(const float* __restrict__ A,
                                  const float* __restrict__ W,
                                  float* __restrict__ out, int n) {
    extern __shared__ float smem[];
    float* As = smem;            // [128][128] row-major
    float* Ws = smem + D * D;    // [128][128] row-major: Ws[k][c]
    int tid = threadIdx.x;
    int row0 = blockIdx.x * 128;

    const float4* W4 = (const float4*)W;
    float4* Ws4 = (float4*)Ws;
    #pragma unroll 4
    for (int i = tid; i < D * D / 4; i += 256) Ws4[i] = W4[i];

    float4* As4 = (float4*)As;
    const float4* A4 = (const float4*)A;
    #pragma unroll 4
    for (int i = tid; i < D * D / 4; i += 256) {
        int m = i >> 5;
        int gm = row0 + m;
        float4 v = make_float4(0.f, 0.f, 0.f, 0.f);
        if (gm < n) v = A4[gm * 32 + (i & 31)];
        As4[i] = v;
    }
    __syncthreads();

    int tx = tid & 15;           // 16 col groups of 8
    int ty = tid >> 4;           // 16 row groups of 8
    u64 acc[8][4];
    #pragma unroll
    for (int i = 0; i < 8; i++)
        #pragma unroll
        for (int j = 0; j < 4; j++) acc[i][j] = 0ull;

    #pragma unroll 2
    for (int k = 0; k < D; ++k) {
        u64 ad[8];
        #pragma unroll
        for (int i = 0; i < 8; i++) ad[i] = dup2(As[(ty * 8 + i) * D + k]);
        const u64* wrow = (const u64*)(Ws + k * D + tx * 8);
        u64 b0 = wrow[0], b1 = wrow[1], b2 = wrow[2], b3 = wrow[3];
        #pragma unroll
        for (int i = 0; i < 8; i++) {
            acc[i][0] = ffma2(ad[i], b0, acc[i][0]);
            acc[i][1] = ffma2(ad[i], b1, acc[i][1]);
            acc[i][2] = ffma2(ad[i], b2, acc[i][2]);
            acc[i][3] = ffma2(ad[i], b3, acc[i][3]);
        }
    }

    #pragma unroll
    for (int i = 0; i < 8; i++) {
        int gm = row0 + ty * 8 + i;
        if (gm < n) {
            u64 dv2 = dup2(g_dinv[gm]);
            u64* orow = (u64*)(out + gm * D + tx * 8);
            #pragma unroll
            for (int j = 0; j < 4; j++) orow[j] = fmul2(acc[i][j], dv2);
        }
    }
}

// ---------------- aggregation: warp per node, pure gather ------------------
__global__ void agg_kernel(const float4* __restrict__ hw,
                           const float* __restrict__ bias,
                           float4* __restrict__ out, int relu) {
    int gt = blockIdx.x * blockDim.x + threadIdx.x;
    int v = gt >> 5;
    int lane = gt & 31;
    if (v >= N_NODES) return;

    float4 acc = hw[v * 32 + lane];            // self loop term
    int s = g_rowptr[v], e = g_rowptr[v + 1];
    int i = s;
    for (; i + 2 <= e; i += 2) {
        int u0 = g_csr[i];
        int u1 = g_csr[i + 1];
        float4 t0 = hw[u0 * 32 + lane];
        float4 t1 = hw[u1 * 32 + lane];
        acc.x += t0.x + t1.x; acc.y += t0.y + t1.y;
        acc.z += t0.z + t1.z; acc.w += t0.w + t1.w;
    }
    if (i < e) {
        int u = g_csr[i];
        float4 t = hw[u * 32 + lane];
        acc.x += t.x; acc.y += t.y; acc.z += t.z; acc.w += t.w;
    }
    float dv = g_dinv[v];
    float4 b = ((const float4*)bias)[lane];
    float4 r;
    r.x = fmaf(dv, acc.x, b.x); r.y = fmaf(dv, acc.y, b.y);
    r.z = fmaf(dv, acc.z, b.z); r.w = fmaf(dv, acc.w, b.w);
    if (relu) {
        r.x = fmaxf(r.x, 0.f); r.y = fmaxf(r.y, 0.f);
        r.z = fmaxf(r.z, 0.f); r.w = fmaxf(r.w, 0.f);
    }
    out[v * 32 + lane] = r;
}

// layer 3: aggregate and pool directly (no h3 store)
__global__ void agg_pool_kernel(const float4* __restrict__ hw,
                                const float* __restrict__ bias,
                                const int* __restrict__ batch) {
    int gt = blockIdx.x * blockDim.x + threadIdx.x;
    int v = gt >> 5;
    int lane = gt & 31;
    if (v >= N_NODES) return;

    float4 acc = hw[v * 32 + lane];
    int s = g_rowptr[v], e = g_rowptr[v + 1];
    int i = s;
    for (; i + 2 <= e; i += 2) {
        int u0 = g_csr[i];
        int u1 = g_csr[i + 1];
        float4 t0 = hw[u0 * 32 + lane];
        float4 t1 = hw[u1 * 32 + lane];
        acc.x += t0.x + t1.x; acc.y += t0.y + t1.y;
        acc.z += t0.z + t1.z; acc.w += t0.w + t1.w;
    }
    if (i < e) {
        int u = g_csr[i];
        float4 t = hw[u * 32 + lane];
        acc.x += t.x; acc.y += t.y; acc.z += t.z; acc.w += t.w;
    }
    float dv = g_dinv[v];
    float4 b = ((const float4*)bias)[lane];
    float4 r;
    r.x = fmaf(dv, acc.x, b.x); r.y = fmaf(dv, acc.y, b.y);
    r.z = fmaf(dv, acc.z, b.z); r.w = fmaf(dv, acc.w, b.w);

    int g = batch[v];
    float* base = &g_gs[g * D + lane * 4];
    atomicAdd(base + 0, r.x);
    atomicAdd(base + 1, r.y);
    atomicAdd(base + 2, r.z);
    atomicAdd(base + 3, r.w);
}

__global__ void count_kernel(const int* __restrict__ batch) {
    int i = blockIdx.x * blockDim.x + threadIdx.x;
    if (i < N_NODES) atomicAdd(&g_gcnt[batch[i]], 1.0f);
}

// pooled @ Wlin + blin -> out[128][3]
__global__ void final_kernel(const float* __restrict__ Wlin,
                             const float* __restrict__ blin,
                             float* __restrict__ out) {
    __shared__ float Ws[D * 3];
    int t = threadIdx.x;          // 128 threads, one graph each
    for (int i = t; i < D * 3; i += 128) Ws[i] = Wlin[i];
    __syncthreads();
    int g = t;
    float inv = 1.0f / fmaxf(g_gcnt[g], 1.0f);
    float o0 = blin[0], o1 = blin[1], o2 = blin[2];
    #pragma unroll 4
    for (int c = 0; c < D; ++c) {
        float p = g_gs[g * D + c] * inv;
        o0 = fmaf(p, Ws[c * 3 + 0], o0);
        o1 = fmaf(p, Ws[c * 3 + 1], o1);
        o2 = fmaf(p, Ws[c * 3 + 2], o2);
    }
    out[g * 3 + 0] = o0;
    out[g * 3 + 1] = o1;
    out[g * 3 + 2] = o2;
}

// ---------------- launch ----------------------------------------------------
extern "C" void kernel_launch(void* const* d_in, const int* in_sizes, int n_in,
                              void* d_out, int out_size) {
    const float* x     = (const float*)d_in[0];
    const int*   ei    = (const int*)d_in[1];
    const int*   batch = (const int*)d_in[2];
    const float* W1 = (const float*)d_in[3];
    const float* b1 = (const float*)d_in[4];
    const float* W2 = (const float*)d_in[5];
    const float* b2 = (const float*)d_in[6];
    const float* W3 = (const float*)d_in[7];
    const float* b3 = (const float*)d_in[8];
    const float* Wlin = (const float*)d_in[9];
    const float* blin = (const float*)d_in[10];
    float* out = (float*)d_out;

    const int* row = ei;             // edge_index[0] = sources
    const int* col = ei + N_EDGES;   // edge_index[1] = targets

    const size_t gemm_smem = 2 * D * D * sizeof(float); // 128 KB
    cudaFuncSetAttribute(gemm_scale_kernel,
                         cudaFuncAttributeMaxDynamicSharedMemorySize,
                         (int)gemm_smem);

    float *hw_p = nullptr, *h_p = nullptr;
    cudaGetSymbolAddress((void**)&hw_p, g_hw);
    cudaGetSymbolAddress((void**)&h_p, g_h);

    const int nodeBlocks = (N_NODES + 255) / 256;
    const int edgeBlocks = (N_EDGES + 255) / 256;
    const int gemmGrid   = (N_NODES + 127) / 128;
    const int aggBlocks  = (N_NODES * 32 + 255) / 256;

    zero_kernel<<<nodeBlocks, 256>>>();
    hist_kernel<<<edgeBlocks, 256>>>(col);
    count_kernel<<<nodeBlocks, 256>>>(batch);
    scan_part_kernel<<<SCAN_BLKS, 1024>>>();
    scan_bsum_kernel<<<1, 1>>>();
    scan_final_kernel<<<(N_NODES + 1023) / 1024, 1024>>>();
    scatter_kernel<<<edgeBlocks, 256>>>(row, col);

    // layer 1
    gemm_scale_kernel<<<gemmGrid, 256, gemm_smem>>>(x, W1, hw_p, N_NODES);
    agg_kernel<<<aggBlocks, 256>>>((const float4*)hw_p, b1, (float4*)h_p, 1);
    // layer 2
    gemm_scale_kernel<<<gemmGrid, 256, gemm_smem>>>(h_p, W2, hw_p, N_NODES);
    agg_kernel<<<aggBlocks, 256>>>((const float4*)hw_p, b2, (float4*)h_p, 1);
    // layer 3 (fused pooling)
    gemm_scale_kernel<<<gemmGrid, 256, gemm_smem>>>(h_p, W3, hw_p, N_NODES);
    agg_pool_kernel<<<aggBlocks, 256>>>((const float4*)hw_p, b3, batch);

    final_kernel<<<1, 128>>>(Wlin, blin, out);
}

// round 3
// speedup vs baseline: 1.2655x; 1.1630x over previous
#include <cuda_runtime.h>
#include <cuda_fp16.h>

#define N_NODES  50000
#define N_EDGES  800000
#define N_GRAPHS 128
#define D        128
#define SCAN_BLKS ((N_NODES + 1023) / 1024)   // 49

typedef unsigned long long u64;

// ---------------- scratch (device globals; no allocation allowed) ----------
__device__ __half g_hw[N_NODES * D];    // GEMM output (scaled by dinv[row]), fp16
__device__ float  g_h [N_NODES * D];    // layer activations, fp32
__device__ int    g_degi[N_NODES];      // in-degree (without self loop)
__device__ float  g_dinv[N_NODES];      // rsqrt(deg+1)
__device__ int    g_scan[N_NODES];      // per-block inclusive scan
__device__ int    g_bsum[SCAN_BLKS];    // per-block totals
__device__ int    g_boff[SCAN_BLKS];    // exclusive offsets of block totals
__device__ int    g_rowptr[N_NODES + 1];// CSR by target node
__device__ int    g_cursor[N_NODES];
__device__ int    g_csr[N_EDGES];       // source node per CSR slot
__device__ float  g_gs[N_GRAPHS * D];   // per-graph feature sums
__device__ float  g_gcnt[N_GRAPHS];     // per-graph node counts

// ---------------- packed helpers -------------------------------------------
__device__ __forceinline__ u64 ffma2(u64 a, u64 b, u64 c) {
    u64 d;
    asm("fma.rn.f32x2 %0, %1, %2, %3;" : "=l"(d) : "l"(a), "l"(b), "l"(c));
    return d;
}
__device__ __forceinline__ u64 fmul2(u64 a, u64 b) {
    u64 d;
    asm("mul.rn.f32x2 %0, %1, %2;" : "=l"(d) : "l"(a), "l"(b));
    return d;
}
__device__ __forceinline__ u64 dup2(float x) {
    u64 d;
    asm("mov.b64 %0, {%1, %1};" : "=l"(d) : "f"(x));
    return d;
}
// packed f32x2 (lo,hi) -> f16x2 word (lo,hi)
__device__ __forceinline__ unsigned f32x2_to_h2(u64 p) {
    unsigned lo, hi, r;
    asm("mov.b64 {%0, %1}, %2;" : "=r"(lo), "=r"(hi) : "l"(p));
    asm("cvt.rn.f16x2.f32 %0, %1, %2;" : "=r"(r)
        : "r"(hi), "r"(lo));   // first operand -> hi half
    return r;
}
// 8 bytes of fp16 (4 values) -> float4
__device__ __forceinline__ float4 h2f4(uint2 p) {
    __half2 a = *reinterpret_cast<__half2*>(&p.x);
    __half2 b = *reinterpret_cast<__half2*>(&p.y);
    float2 fa = __half22float2(a);
    float2 fb = __half22float2(b);
    return make_float4(fa.x, fa.y, fb.x, fb.y);
}
__device__ __forceinline__ void acc4(float4& a, float4 t) {
    a.x += t.x; a.y += t.y; a.z += t.z; a.w += t.w;
}

// ---------------- setup kernels --------------------------------------------
__global__ void zero_kernel() {
    int i = blockIdx.x * blockDim.x + threadIdx.x;
    if (i < N_NODES) g_degi[i] = 0;
    if (i < N_GRAPHS * D) g_gs[i] = 0.f;
    if (i < N_GRAPHS) g_gcnt[i] = 0.f;
}

__global__ void hist_kernel(const int* __restrict__ col) {
    int e = blockIdx.x * blockDim.x + threadIdx.x;
    if (e < N_EDGES) atomicAdd(&g_degi[col[e]], 1);
}

// phase 1: per-block shuffle scan (1024 threads), also compute dinv
__global__ void scan_part_kernel() {
    __shared__ int wsum[32];
    int tid  = threadIdx.x;
    int lane = tid & 31;
    int wid  = tid >> 5;
    int idx  = blockIdx.x * 1024 + tid;
    int v = (idx < N_NODES) ? g_degi[idx] : 0;
    if (idx < N_NODES) g_dinv[idx] = rsqrtf((float)(v + 1));

    int x = v;
    #pragma unroll
    for (int s = 1; s < 32; s <<= 1) {
        int t = __shfl_up_sync(0xffffffffu, x, s);
        if (lane >= s) x += t;
    }
    if (lane == 31) wsum[wid] = x;
    __syncthreads();
    if (wid == 0) {
        int y = wsum[lane];
        #pragma unroll
        for (int s = 1; s < 32; s <<= 1) {
            int t = __shfl_up_sync(0xffffffffu, y, s);
            if (lane >= s) y += t;
        }
        wsum[lane] = y;
    }
    __syncthreads();
    int incl = x + (wid ? wsum[wid - 1] : 0);
    if (idx < N_NODES) g_scan[idx] = incl;
    if (tid == 1023) g_bsum[blockIdx.x] = incl;
}

// phase 2: warp-parallel scan of 49 block totals
__global__ void scan_bsum_kernel() {
    int lane = threadIdx.x;
    int x0 = (lane < SCAN_BLKS) ? g_bsum[lane] : 0;
    int x1 = (lane + 32 < SCAN_BLKS) ? g_bsum[lane + 32] : 0;
    int i0 = x0;
    #pragma unroll
    for (int s = 1; s < 32; s <<= 1) {
        int t = __shfl_up_sync(0xffffffffu, i0, s);
        if (lane >= s) i0 += t;
    }
    int tot0 = __shfl_sync(0xffffffffu, i0, 31);
    int i1 = x1;
    #pragma unroll
    for (int s = 1; s < 32; s <<= 1) {
        int t = __shfl_up_sync(0xffffffffu, i1, s);
        if (lane >= s) i1 += t;
    }
    if (lane < SCAN_BLKS) g_boff[lane] = i0 - x0;
    if (lane + 32 < SCAN_BLKS) g_boff[lane + 32] = tot0 + i1 - x1;
}

// phase 3: finalize rowptr + cursor
__global__ void scan_final_kernel() {
    int idx = blockIdx.x * blockDim.x + threadIdx.x;
    if (idx == 0) g_rowptr[0] = 0;
    if (idx < N_NODES) {
        int incl = g_scan[idx] + g_boff[idx >> 10];
        g_rowptr[idx + 1] = incl;
        g_cursor[idx]     = incl - g_degi[idx];
    }
}

__global__ void scatter_kernel(const int* __restrict__ row,
                               const int* __restrict__ col) {
    int e = blockIdx.x * blockDim.x + threadIdx.x;
    if (e < N_EDGES) {
        int c = col[e];
        int p = atomicAdd(&g_cursor[c], 1);
        g_csr[p] = row[e];
    }
}

// ---------------- fused GEMM: hw[n] = fp16( dinv[n] * (A[n] @ W) ) ----------
__global__ void gemm_scale_kernel(const float* __restrict__ A,
                                  const float* __restrict__ W,
                                  __half* __restrict__ out, int n) {
    extern __shared__ float smem[];
    float* As = smem;            // [128][128] row-major
    float* Ws = smem + D * D;    // [128][128] row-major: Ws[k][c]
    int tid = threadIdx.x;
    int row0 = blockIdx.x * 128;

    const float4* W4 = (const float4*)W;
    float4* Ws4 = (float4*)Ws;
    #pragma unroll 4
    for (int i = tid; i < D * D / 4; i += 256) Ws4[i] = W4[i];

    float4* As4 = (float4*)As;
    const float4* A4 = (const float4*)A;
    #pragma unroll 4
    for (int i = tid; i < D * D / 4; i += 256) {
        int m = i >> 5;
        int gm = row0 + m;
        float4 v = make_float4(0.f, 0.f, 0.f, 0.f);
        if (gm < n) v = A4[gm * 32 + (i & 31)];
        As4[i] = v;
    }
    __syncthreads();

    int tx = tid & 15;           // 16 col groups of 8
    int ty = tid >> 4;           // 16 row groups of 8
    u64 acc[8][4];
    #pragma unroll
    for (int i = 0; i < 8; i++)
        #pragma unroll
        for (int j = 0; j < 4; j++) acc[i][j] = 0ull;

    #pragma unroll 2
    for (int k = 0; k < D; ++k) {
        u64 ad[8];
        #pragma unroll
        for (int i = 0; i < 8; i++) ad[i] = dup2(As[(ty * 8 + i) * D + k]);
        const u64* wrow = (const u64*)(Ws + k * D + tx * 8);
        u64 b0 = wrow[0], b1 = wrow[1], b2 = wrow[2], b3 = wrow[3];
        #pragma unroll
        for (int i = 0; i < 8; i++) {
            acc[i][0] = ffma2(ad[i], b0, acc[i][0]);
            acc[i][1] = ffma2(ad[i], b1, acc[i][1]);
            acc[i][2] = ffma2(ad[i], b2, acc[i][2]);
            acc[i][3] = ffma2(ad[i], b3, acc[i][3]);
        }
    }

    #pragma unroll
    for (int i = 0; i < 8; i++) {
        int gm = row0 + ty * 8 + i;
        if (gm < n) {
            u64 dv2 = dup2(g_dinv[gm]);
            uint4 o;
            o.x = f32x2_to_h2(fmul2(acc[i][0], dv2));
            o.y = f32x2_to_h2(fmul2(acc[i][1], dv2));
            o.z = f32x2_to_h2(fmul2(acc[i][2], dv2));
            o.w = f32x2_to_h2(fmul2(acc[i][3], dv2));
            ((uint4*)(out + gm * D))[tx] = o;
        }
    }
}

// ---------------- aggregation: warp per node, fp16 gather, fp32 acc --------
__global__ void agg_kernel(const uint2* __restrict__ hw,   // fp16 rows, 32 uint2/row
                           const float* __restrict__ bias,
                           float4* __restrict__ out, int relu) {
    int gt = blockIdx.x * blockDim.x + threadIdx.x;
    int v = gt >> 5;
    int lane = gt & 31;
    if (v >= N_NODES) return;

    float4 acc = h2f4(hw[v * 32 + lane]);      // self loop term
    int s = g_rowptr[v], e = g_rowptr[v + 1];
    int i = s;
    for (; i + 4 <= e; i += 4) {
        int u0 = g_csr[i], u1 = g_csr[i + 1];
        int u2 = g_csr[i + 2], u3 = g_csr[i + 3];
        uint2 p0 = hw[u0 * 32 + lane];
        uint2 p1 = hw[u1 * 32 + lane];
        uint2 p2 = hw[u2 * 32 + lane];
        uint2 p3 = hw[u3 * 32 + lane];
        acc4(acc, h2f4(p0)); acc4(acc, h2f4(p1));
        acc4(acc, h2f4(p2)); acc4(acc, h2f4(p3));
    }
    for (; i < e; ++i) {
        acc4(acc, h2f4(hw[g_csr[i] * 32 + lane]));
    }
    float dv = g_dinv[v];
    float4 b = ((const float4*)bias)[lane];
    float4 r;
    r.x = fmaf(dv, acc.x, b.x); r.y = fmaf(dv, acc.y, b.y);
    r.z = fmaf(dv, acc.z, b.z); r.w = fmaf(dv, acc.w, b.w);
    if (relu) {
        r.x = fmaxf(r.x, 0.f); r.y = fmaxf(r.y, 0.f);
        r.z = fmaxf(r.z, 0.f); r.w = fmaxf(r.w, 0.f);
    }
    out[v * 32 + lane] = r;
}

// layer 3: aggregate and pool directly (no h3 store)
__global__ void agg_pool_kernel(const uint2* __restrict__ hw,
                                const float* __restrict__ bias,
                                const int* __restrict__ batch) {
    int gt = blockIdx.x * blockDim.x + threadIdx.x;
    int v = gt >> 5;
    int lane = gt & 31;
    if (v >= N_NODES) return;

    float4 acc = h2f4(hw[v * 32 + lane]);
    int s = g_rowptr[v], e = g_rowptr[v + 1];
    int i = s;
    for (; i + 4 <= e; i += 4) {
        int u0 = g_csr[i], u1 = g_csr[i + 1];
        int u2 = g_csr[i + 2], u3 = g_csr[i + 3];
        uint2 p0 = hw[u0 * 32 + lane];
        uint2 p1 = hw[u1 * 32 + lane];
        uint2 p2 = hw[u2 * 32 + lane];
        uint2 p3 = hw[u3 * 32 + lane];
        acc4(acc, h2f4(p0)); acc4(acc, h2f4(p1));
        acc4(acc, h2f4(p2)); acc4(acc, h2f4(p3));
    }
    for (; i < e; ++i) {
        acc4(acc, h2f4(hw[g_csr[i] * 32 + lane]));
    }
    float dv = g_dinv[v];
    float4 b = ((const float4*)bias)[lane];
    float4 r;
    r.x = fmaf(dv, acc.x, b.x); r.y = fmaf(dv, acc.y, b.y);
    r.z = fmaf(dv, acc.z, b.z); r.w = fmaf(dv, acc.w, b.w);

    int g = batch[v];
    float* base = &g_gs[g * D + lane * 4];
    atomicAdd(base + 0, r.x);
    atomicAdd(base + 1, r.y);
    atomicAdd(base + 2, r.z);
    atomicAdd(base + 3, r.w);
}

__global__ void count_kernel(const int* __restrict__ batch) {
    int i = blockIdx.x * blockDim.x + threadIdx.x;
    if (i < N_NODES) atomicAdd(&g_gcnt[batch[i]], 1.0f);
}

// pooled @ Wlin + blin -> out[128][3]
__global__ void final_kernel(const float* __restrict__ Wlin,
                             const float* __restrict__ blin,
                             float* __restrict__ out) {
    __shared__ float Ws[D * 3];
    int t = threadIdx.x;          // 128 threads, one graph each
    for (int i = t; i < D * 3; i += 128) Ws[i] = Wlin[i];
    __syncthreads();
    int g = t;
    float inv = 1.0f / fmaxf(g_gcnt[g], 1.0f);
    float o0 = blin[0], o1 = blin[1], o2 = blin[2];
    #pragma unroll 4
    for (int c = 0; c < D; ++c) {
        float p = g_gs[g * D + c] * inv;
        o0 = fmaf(p, Ws[c * 3 + 0], o0);
        o1 = fmaf(p, Ws[c * 3 + 1], o1);
        o2 = fmaf(p, Ws[c * 3 + 2], o2);
    }
    out[g * 3 + 0] = o0;
    out[g * 3 + 1] = o1;
    out[g * 3 + 2] = o2;
}

// ---------------- launch ----------------------------------------------------
extern "C" void kernel_launch(void* const* d_in, const int* in_sizes, int n_in,
                              void* d_out, int out_size) {
    const float* x     = (const float*)d_in[0];
    const int*   ei    = (const int*)d_in[1];
    const int*   batch = (const int*)d_in[2];
    const float* W1 = (const float*)d_in[3];
    const float* b1 = (const float*)d_in[4];
    const float* W2 = (const float*)d_in[5];
    const float* b2 = (const float*)d_in[6];
    const float* W3 = (const float*)d_in[7];
    const float* b3 = (const float*)d_in[8];
    const float* Wlin = (const float*)d_in[9];
    const float* blin = (const float*)d_in[10];
    float* out = (float*)d_out;

    const int* row = ei;             // edge_index[0] = sources
    const int* col = ei + N_EDGES;   // edge_index[1] = targets

    const size_t gemm_smem = 2 * D * D * sizeof(float); // 128 KB
    cudaFuncSetAttribute(gemm_scale_kernel,
                         cudaFuncAttributeMaxDynamicSharedMemorySize,
                         (int)gemm_smem);

    __half* hw_p = nullptr;
    float*  h_p  = nullptr;
    cudaGetSymbolAddress((void**)&hw_p, g_hw);
    cudaGetSymbolAddress((void**)&h_p, g_h);

    const int nodeBlocks = (N_NODES + 255) / 256;
    const int edgeBlocks = (N_EDGES + 255) / 256;
    const int gemmGrid   = (N_NODES + 127) / 128;
    const int aggBlocks  = (N_NODES * 32 + 255) / 256;

    zero_kernel<<<nodeBlocks, 256>>>();
    hist_kernel<<<edgeBlocks, 256>>>(col);
    count_kernel<<<nodeBlocks, 256>>>(batch);
    scan_part_kernel<<<SCAN_BLKS, 1024>>>();
    scan_bsum_kernel<<<1, 32>>>();
    scan_final_kernel<<<(N_NODES + 1023) / 1024, 1024>>>();
    scatter_kernel<<<edgeBlocks, 256>>>(row, col);

    // layer 1
    gemm_scale_kernel<<<gemmGrid, 256, gemm_smem>>>(x, W1, hw_p, N_NODES);
    agg_kernel<<<aggBlocks, 256>>>((const uint2*)hw_p, b1, (float4*)h_p, 1);
    // layer 2
    gemm_scale_kernel<<<gemmGrid, 256, gemm_smem>>>(h_p, W2, hw_p, N_NODES);
    agg_kernel<<<aggBlocks, 256>>>((const uint2*)hw_p, b2, (float4*)h_p, 1);
    // layer 3 (fused pooling)
    gemm_scale_kernel<<<gemmGrid, 256, gemm_smem>>>(h_p, W3, hw_p, N_NODES);
    agg_pool_kernel<<<aggBlocks, 256>>>((const uint2*)hw_p, b3, batch);

    final_kernel<<<1, 128>>>(Wlin, blin, out);
}

// round 5
// speedup vs baseline: 1.8196x; 1.4378x over previous
#include <cuda_runtime.h>
#include <cuda_bf16.h>
#include <cstdint>

#define N_NODES  50000
#define N_EDGES  800000
#define N_GRAPHS 128
#define D        128
#define SCAN_BLKS ((N_NODES + 1023) / 1024)   // 49

// ---------------- scratch (device globals; no allocation allowed) ----------
__device__ __nv_bfloat16 g_xb[N_NODES * D];   // x converted to bf16
__device__ __nv_bfloat16 g_hw[N_NODES * D];   // GEMM output (scaled by dinv), bf16
__device__ __nv_bfloat16 g_hb[N_NODES * D];   // layer activations, bf16
__device__ __nv_bfloat16 g_wt[3 * D * D];     // transposed weights [N][K] bf16
__device__ int    g_degi[N_NODES];
__device__ float  g_dinv[N_NODES];
__device__ int    g_scan[N_NODES];
__device__ int    g_bsum[SCAN_BLKS];
__device__ int    g_boff[SCAN_BLKS];
__device__ int    g_rowptr[N_NODES + 1];
__device__ int    g_cursor[N_NODES];
__device__ int    g_csr[N_EDGES];
__device__ float  g_gs[N_GRAPHS * D];
__device__ float  g_gcnt[N_GRAPHS];

// ---------------- small helpers --------------------------------------------
__device__ __forceinline__ unsigned bfpack(float lo, float hi) {
    unsigned r;
    asm("cvt.rn.bf16x2.f32 %0, %1, %2;" : "=r"(r) : "f"(hi), "f"(lo));
    return r;
}
__device__ __forceinline__ float4 b2f4(uint2 p) {
    __nv_bfloat162 a = *reinterpret_cast<__nv_bfloat162*>(&p.x);
    __nv_bfloat162 b = *reinterpret_cast<__nv_bfloat162*>(&p.y);
    float2 fa = __bfloat1622float2(a);
    float2 fb = __bfloat1622float2(b);
    return make_float4(fa.x, fa.y, fb.x, fb.y);
}
__device__ __forceinline__ void acc4(float4& a, float4 t) {
    a.x += t.x; a.y += t.y; a.z += t.z; a.w += t.w;
}
__device__ __forceinline__ uint32_t smem_u32(const void* p) {
    uint32_t a;
    asm("{ .reg .u64 t; cvta.to.shared.u64 t, %1; cvt.u32.u64 %0, t; }"
        : "=r"(a) : "l"(p));
    return a;
}

// ---------------- mma helpers ------------------------------------------------
__device__ __forceinline__ void ldsm_x4(uint32_t& r0, uint32_t& r1,
                                        uint32_t& r2, uint32_t& r3,
                                        uint32_t addr) {
    asm volatile("ldmatrix.sync.aligned.m8n8.x4.shared.b16 {%0,%1,%2,%3}, [%4];"
                 : "=r"(r0), "=r"(r1), "=r"(r2), "=r"(r3) : "r"(addr));
}
__device__ __forceinline__ void ldsm_x2(uint32_t& r0, uint32_t& r1,
                                        uint32_t addr) {
    asm volatile("ldmatrix.sync.aligned.m8n8.x2.shared.b16 {%0,%1}, [%2];"
                 : "=r"(r0), "=r"(r1) : "r"(addr));
}
__device__ __forceinline__ void mma16816(float& d0, float& d1, float& d2, float& d3,
                                         uint32_t a0, uint32_t a1, uint32_t a2,
                                         uint32_t a3, uint32_t b0, uint32_t b1) {
    asm volatile(
        "mma.sync.aligned.m16n8k16.row.col.f32.bf16.bf16.f32 "
        "{%0,%1,%2,%3}, {%4,%5,%6,%7}, {%8,%9}, {%0,%1,%2,%3};"
        : "+f"(d0), "+f"(d1), "+f"(d2), "+f"(d3)
        : "r"(a0), "r"(a1), "r"(a2), "r"(a3), "r"(b0), "r"(b1));
}

// ---------------- setup kernels --------------------------------------------
__global__ void zero_kernel() {
    int i = blockIdx.x * blockDim.x + threadIdx.x;
    if (i < N_NODES) g_degi[i] = 0;
    if (i < N_GRAPHS * D) g_gs[i] = 0.f;
    if (i < N_GRAPHS) g_gcnt[i] = 0.f;
}

__global__ void hist_kernel(const int* __restrict__ col) {
    int e = blockIdx.x * blockDim.x + threadIdx.x;
    if (e < N_EDGES) atomicAdd(&g_degi[col[e]], 1);
}

__global__ void count_kernel(const int* __restrict__ batch) {
    int i = blockIdx.x * blockDim.x + threadIdx.x;
    if (i < N_NODES) atomicAdd(&g_gcnt[batch[i]], 1.0f);
}

__global__ void scan_part_kernel() {
    __shared__ int wsum[32];
    int tid = threadIdx.x, lane = tid & 31, wid = tid >> 5;
    int idx = blockIdx.x * 1024 + tid;
    int v = (idx < N_NODES) ? g_degi[idx] : 0;
    if (idx < N_NODES) g_dinv[idx] = rsqrtf((float)(v + 1));
    int x = v;
    #pragma unroll
    for (int s = 1; s < 32; s <<= 1) {
        int t = __shfl_up_sync(0xffffffffu, x, s);
        if (lane >= s) x += t;
    }
    if (lane == 31) wsum[wid] = x;
    __syncthreads();
    if (wid == 0) {
        int y = wsum[lane];
        #pragma unroll
        for (int s = 1; s < 32; s <<= 1) {
            int t = __shfl_up_sync(0xffffffffu, y, s);
            if (lane >= s) y += t;
        }
        wsum[lane] = y;
    }
    __syncthreads();
    int incl = x + (wid ? wsum[wid - 1] : 0);
    if (idx < N_NODES) g_scan[idx] = incl;
    if (tid == 1023) g_bsum[blockIdx.x] = incl;
}

__global__ void scan_bsum_kernel() {
    int lane = threadIdx.x;
    int x0 = (lane < SCAN_BLKS) ? g_bsum[lane] : 0;
    int x1 = (lane + 32 < SCAN_BLKS) ? g_bsum[lane + 32] : 0;
    int i0 = x0;
    #pragma unroll
    for (int s = 1; s < 32; s <<= 1) {
        int t = __shfl_up_sync(0xffffffffu, i0, s);
        if (lane >= s) i0 += t;
    }
    int tot0 = __shfl_sync(0xffffffffu, i0, 31);
    int i1 = x1;
    #pragma unroll
    for (int s = 1; s < 32; s <<= 1) {
        int t = __shfl_up_sync(0xffffffffu, i1, s);
        if (lane >= s) i1 += t;
    }
    if (lane < SCAN_BLKS) g_boff[lane] = i0 - x0;
    if (lane + 32 < SCAN_BLKS) g_boff[lane + 32] = tot0 + i1 - x1;
}

__global__ void scan_final_kernel() {
    int idx = blockIdx.x * blockDim.x + threadIdx.x;
    if (idx == 0) g_rowptr[0] = 0;
    if (idx < N_NODES) {
        int incl = g_scan[idx] + g_boff[idx >> 10];
        g_rowptr[idx + 1] = incl;
        g_cursor[idx]     = incl - g_degi[idx];
    }
}

__global__ void scatter_kernel(const int* __restrict__ row,
                               const int* __restrict__ col) {
    int e = blockIdx.x * blockDim.x + threadIdx.x;
    if (e < N_EDGES) {
        int c = col[e];
        int p = atomicAdd(&g_cursor[c], 1);
        g_csr[p] = row[e];
    }
}

// convert x -> bf16 (vectorized, 4 floats per thread)
__global__ void conv_x_kernel(const float* __restrict__ x) {
    int i = blockIdx.x * blockDim.x + threadIdx.x;
    if (i < N_NODES * (D / 4)) {
        float4 v = ((const float4*)x)[i];
        uint2 o;
        o.x = bfpack(v.x, v.y);
        o.y = bfpack(v.z, v.w);
        ((uint2*)g_xb)[i] = o;
    }
}

// transpose + convert weights: g_wt[l][n][k] = bf16(W_l[k][n])
__global__ void prep_w_kernel(const float* __restrict__ W1,
                              const float* __restrict__ W2,
                              const float* __restrict__ W3) {
    int idx = blockIdx.x * blockDim.x + threadIdx.x;
    if (idx >= 3 * D * D) return;
    int l = idx >> 14;
    int r = idx & (D * D - 1);
    int k = r >> 7, n = r & 127;
    const float* W = (l == 0) ? W1 : ((l == 1) ? W2 : W3);
    g_wt[l * D * D + n * D + k] = __float2bfloat16(W[k * D + n]);
}

// ---------------- HMMA GEMM: out[m] = bf16( dinv[m] * (in[m] @ W) ) --------
// 256 threads (8 warps). Each warp: 16 M-rows x full N=128.
// smem: A[128][136] bf16 + B[128][136] bf16, padded rows (272 B) for
// conflict-free ldmatrix.
#define SM_STRIDE 136                       // bf16 elems per padded row
#define SM_ROWB   (SM_STRIDE * 2)           // 272 bytes
#define SM_A_OFF  0
#define SM_B_OFF  (128 * SM_ROWB)           // 34816
#define SM_TOT    (2 * 128 * SM_ROWB)       // 69632

__global__ void __launch_bounds__(256, 2)
mma_gemm_kernel(const __nv_bfloat16* __restrict__ in,
                const __nv_bfloat16* __restrict__ Wt,
                __nv_bfloat16* __restrict__ out, int n) {
    extern __shared__ char smem[];
    uint32_t sb = smem_u32(smem);
    int tid = threadIdx.x, wid = tid >> 5, lane = tid & 31;
    int row0 = blockIdx.x * 128;

    // stage A (zero-pad rows beyond n) and B
    const uint4* Ain = (const uint4*)(in + (size_t)row0 * D);
    const uint4* Bin = (const uint4*)Wt;
    #pragma unroll 4
    for (int i = tid; i < 2048; i += 256) {
        int r = i >> 4, g = i & 15;
        uint4 va = make_uint4(0u, 0u, 0u, 0u);
        if (row0 + r < n) va = Ain[i];
        *(uint4*)(smem + SM_A_OFF + r * SM_ROWB + g * 16) = va;
        *(uint4*)(smem + SM_B_OFF + r * SM_ROWB + g * 16) = Bin[i];
    }
    __syncthreads();

    // per-lane ldmatrix base addresses
    int m_base = wid * 16;
    // A: lane l -> row m_base + (l%16), col 8*(l/16)
    uint32_t a_addr = sb + SM_A_OFF
                    + (uint32_t)(m_base + (lane & 15)) * SM_ROWB
                    + (uint32_t)(lane >> 4) * 16;     // 8 bf16 = 16 B
    // B: lane l(<16) -> row n_tile*8 + (l%8), col 8*((l/8)&1)
    uint32_t b_addr = sb + SM_B_OFF
                    + (uint32_t)(lane & 7) * SM_ROWB
                    + (uint32_t)((lane >> 3) & 1) * 16;

    float acc[16][4];
    #pragma unroll
    for (int j = 0; j < 16; j++)
        #pragma unroll
        for (int q = 0; q < 4; q++) acc[j][q] = 0.f;

    #pragma unroll
    for (int kk = 0; kk < 8; kk++) {
        uint32_t a0, a1, a2, a3;
        ldsm_x4(a0, a1, a2, a3, a_addr + kk * 32);    // 16 bf16 = 32 B per kstep
        #pragma unroll
        for (int j = 0; j < 16; j++) {
            uint32_t b0, b1;
            ldsm_x2(b0, b1, b_addr + (uint32_t)j * 8 * SM_ROWB + kk * 32);
            mma16816(acc[j][0], acc[j][1], acc[j][2], acc[j][3],
                     a0, a1, a2, a3, b0, b1);
        }
    }

    // epilogue: scale by dinv[m], pack bf16, store
    int quad = lane >> 2;          // 0..7
    int tcol = (lane & 3) * 2;     // 0,2,4,6
    int r0 = row0 + m_base + quad;
    int r1 = r0 + 8;
    float dv0 = (r0 < n) ? g_dinv[r0] : 0.f;
    float dv1 = (r1 < n) ? g_dinv[r1] : 0.f;
    unsigned* o0 = (unsigned*)(out + (size_t)(r0 < n ? r0 : 0) * D);
    unsigned* o1 = (unsigned*)(out + (size_t)(r1 < n ? r1 : 0) * D);
    #pragma unroll
    for (int j = 0; j < 16; j++) {
        int nc = j * 8 + tcol;
        if (r0 < n) o0[nc >> 1] = bfpack(acc[j][0] * dv0, acc[j][1] * dv0);
        if (r1 < n) o1[nc >> 1] = bfpack(acc[j][2] * dv1, acc[j][3] * dv1);
    }
}

// ---------------- aggregation: warp per node, bf16 gather, fp32 acc --------
__global__ void agg_kernel(const uint2* __restrict__ hw,
                           const float* __restrict__ bias,
                           uint2* __restrict__ out, int relu) {
    int gt = blockIdx.x * blockDim.x + threadIdx.x;
    int v = gt >> 5;
    int lane = gt & 31;
    if (v >= N_NODES) return;

    float4 acc = b2f4(hw[v * 32 + lane]);
    int s = g_rowptr[v], e = g_rowptr[v + 1];
    int i = s;
    for (; i + 4 <= e; i += 4) {
        int u0 = g_csr[i], u1 = g_csr[i + 1];
        int u2 = g_csr[i + 2], u3 = g_csr[i + 3];
        uint2 p0 = hw[u0 * 32 + lane];
        uint2 p1 = hw[u1 * 32 + lane];
        uint2 p2 = hw[u2 * 32 + lane];
        uint2 p3 = hw[u3 * 32 + lane];
        acc4(acc, b2f4(p0)); acc4(acc, b2f4(p1));
        acc4(acc, b2f4(p2)); acc4(acc, b2f4(p3));
    }
    for (; i < e; ++i) acc4(acc, b2f4(hw[g_csr[i] * 32 + lane]));

    float dv = g_dinv[v];
    float4 b = ((const float4*)bias)[lane];
    float4 r;
    r.x = fmaf(dv, acc.x, b.x); r.y = fmaf(dv, acc.y, b.y);
    r.z = fmaf(dv, acc.z, b.z); r.w = fmaf(dv, acc.w, b.w);
    if (relu) {
        r.x = fmaxf(r.x, 0.f); r.y = fmaxf(r.y, 0.f);
        r.z = fmaxf(r.z, 0.f); r.w = fmaxf(r.w, 0.f);
    }
    out[v * 32 + lane] = make_uint2(bfpack(r.x, r.y), bfpack(r.z, r.w));
}

__global__ void agg_pool_kernel(const uint2* __restrict__ hw,
                                const float* __restrict__ bias,
                                const int* __restrict__ batch) {
    int gt = blockIdx.x * blockDim.x + threadIdx.x;
    int v = gt >> 5;
    int lane = gt & 31;
    if (v >= N_NODES) return;

    float4 acc = b2f4(hw[v * 32 + lane]);
    int s = g_rowptr[v], e = g_rowptr[v + 1];
    int i = s;
    for (; i + 4 <= e; i += 4) {
        int u0 = g_csr[i], u1 = g_csr[i + 1];
        int u2 = g_csr[i + 2], u3 = g_csr[i + 3];
        uint2 p0 = hw[u0 * 32 + lane];
        uint2 p1 = hw[u1 * 32 + lane];
        uint2 p2 = hw[u2 * 32 + lane];
        uint2 p3 = hw[u3 * 32 + lane];
        acc4(acc, b2f4(p0)); acc4(acc, b2f4(p1));
        acc4(acc, b2f4(p2)); acc4(acc, b2f4(p3));
    }
    for (; i < e; ++i) acc4(acc, b2f4(hw[g_csr[i] * 32 + lane]));

    float dv = g_dinv[v];
    float4 b = ((const float4*)bias)[lane];
    float4 r;
    r.x = fmaf(dv, acc.x, b.x); r.y = fmaf(dv, acc.y, b.y);
    r.z = fmaf(dv, acc.z, b.z); r.w = fmaf(dv, acc.w, b.w);

    int g = batch[v];
    float* base = &g_gs[g * D + lane * 4];
    atomicAdd(base + 0, r.x);
    atomicAdd(base + 1, r.y);
    atomicAdd(base + 2, r.z);
    atomicAdd(base + 3, r.w);
}

__global__ void final_kernel(const float* __restrict__ Wlin,
                             const float* __restrict__ blin,
                             float* __restrict__ out) {
    __shared__ float Ws[D * 3];
    int t = threadIdx.x;
    for (int i = t; i < D * 3; i += 128) Ws[i] = Wlin[i];
    __syncthreads();
    int g = t;
    float inv = 1.0f / fmaxf(g_gcnt[g], 1.0f);
    float o0 = blin[0], o1 = blin[1], o2 = blin[2];
    #pragma unroll 4
    for (int c = 0; c < D; ++c) {
        float p = g_gs[g * D + c] * inv;
        o0 = fmaf(p, Ws[c * 3 + 0], o0);
        o1 = fmaf(p, Ws[c * 3 + 1], o1);
        o2 = fmaf(p, Ws[c * 3 + 2], o2);
    }
    out[g * 3 + 0] = o0;
    out[g * 3 + 1] = o1;
    out[g * 3 + 2] = o2;
}

// ---------------- launch ----------------------------------------------------
extern "C" void kernel_launch(void* const* d_in, const int* in_sizes, int n_in,
                              void* d_out, int out_size) {
    const float* x     = (const float*)d_in[0];
    const int*   ei    = (const int*)d_in[1];
    const int*   batch = (const int*)d_in[2];
    const float* W1 = (const float*)d_in[3];
    const float* b1 = (const float*)d_in[4];
    const float* W2 = (const float*)d_in[5];
    const float* b2 = (const float*)d_in[6];
    const float* W3 = (const float*)d_in[7];
    const float* b3 = (const float*)d_in[8];
    const float* Wlin = (const float*)d_in[9];
    const float* blin = (const float*)d_in[10];
    float* out = (float*)d_out;

    const int* row = ei;
    const int* col = ei + N_EDGES;

    cudaFuncSetAttribute(mma_gemm_kernel,
                         cudaFuncAttributeMaxDynamicSharedMemorySize, SM_TOT);

    __nv_bfloat16 *xb_p = nullptr, *hw_p = nullptr, *hb_p = nullptr, *wt_p = nullptr;
    cudaGetSymbolAddress((void**)&xb_p, g_xb);
    cudaGetSymbolAddress((void**)&hw_p, g_hw);
    cudaGetSymbolAddress((void**)&hb_p, g_hb);
    cudaGetSymbolAddress((void**)&wt_p, g_wt);

    const int nodeBlocks = (N_NODES + 255) / 256;
    const int edgeBlocks = (N_EDGES + 255) / 256;
    const int gemmGrid   = (N_NODES + 127) / 128;
    const int aggBlocks  = (N_NODES * 32 + 255) / 256;
    const int convBlocks = (N_NODES * 32 + 255) / 256;

    zero_kernel<<<nodeBlocks, 256>>>();
    hist_kernel<<<edgeBlocks, 256>>>(col);
    count_kernel<<<nodeBlocks, 256>>>(batch);
    scan_part_kernel<<<SCAN_BLKS, 1024>>>();
    scan_bsum_kernel<<<1, 32>>>();
    scan_final_kernel<<<(N_NODES + 1023) / 1024, 1024>>>();
    scatter_kernel<<<edgeBlocks, 256>>>(row, col);
    conv_x_kernel<<<convBlocks, 256>>>(x);
    prep_w_kernel<<<(3 * D * D + 255) / 256, 256>>>(W1, W2, W3);

    // layer 1
    mma_gemm_kernel<<<gemmGrid, 256, SM_TOT>>>(xb_p, wt_p, hw_p, N_NODES);
    agg_kernel<<<aggBlocks, 256>>>((const uint2*)hw_p, b1, (uint2*)hb_p, 1);
    // layer 2
    mma_gemm_kernel<<<gemmGrid, 256, SM_TOT>>>(hb_p, wt_p + D * D, hw_p, N_NODES);
    agg_kernel<<<aggBlocks, 256>>>((const uint2*)hw_p, b2, (uint2*)hb_p, 1);
    // layer 3 (fused pooling)
    mma_gemm_kernel<<<gemmGrid, 256, SM_TOT>>>(hb_p, wt_p + 2 * D * D, hw_p, N_NODES);
    agg_pool_kernel<<<aggBlocks, 256>>>((const uint2*)hw_p, b3, batch);

    final_kernel<<<1, 128>>>(Wlin, blin, out);
}

// round 6
// speedup vs baseline: 1.8738x; 1.0298x over previous
#include <cuda_runtime.h>
#include <cuda_fp16.h>
#include <cstdint>

#define N_NODES  50000
#define N_EDGES  800000
#define N_GRAPHS 128
#define D        128
#define SCAN_BLKS ((N_NODES + 1023) / 1024)   // 49

// ---------------- scratch (device globals; no allocation allowed) ----------
__device__ __half g_xb[N_NODES * D];   // x converted to fp16
__device__ __half g_hw[N_NODES * D];   // GEMM output (scaled by dinv), fp16
__device__ __half g_hb[N_NODES * D];   // layer activations, fp16
__device__ __half g_wt[3 * D * D];     // transposed weights [N][K] fp16
__device__ int    g_degi[N_NODES];
__device__ float  g_dinv[N_NODES];
__device__ int    g_scan[N_NODES];
__device__ int    g_bsum[SCAN_BLKS];
__device__ int    g_boff[SCAN_BLKS];
__device__ int    g_rowptr[N_NODES + 1];
__device__ int    g_cursor[N_NODES];
__device__ int    g_csr[N_EDGES];
__device__ float  g_gs[N_GRAPHS * D];
__device__ float  g_gcnt[N_GRAPHS];

// ---------------- small helpers --------------------------------------------
__device__ __forceinline__ unsigned hpack(float lo, float hi) {
    unsigned r;
    asm("cvt.rn.f16x2.f32 %0, %1, %2;" : "=r"(r) : "f"(hi), "f"(lo));
    return r;
}
__device__ __forceinline__ float4 h2f4(uint2 p) {
    __half2 a = *reinterpret_cast<__half2*>(&p.x);
    __half2 b = *reinterpret_cast<__half2*>(&p.y);
    float2 fa = __half22float2(a);
    float2 fb = __half22float2(b);
    return make_float4(fa.x, fa.y, fb.x, fb.y);
}
__device__ __forceinline__ void acc4(float4& a, float4 t) {
    a.x += t.x; a.y += t.y; a.z += t.z; a.w += t.w;
}
__device__ __forceinline__ uint32_t smem_u32(const void* p) {
    uint32_t a;
    asm("{ .reg .u64 t; cvta.to.shared.u64 t, %1; cvt.u32.u64 %0, t; }"
        : "=r"(a) : "l"(p));
    return a;
}

// ---------------- mma helpers ------------------------------------------------
__device__ __forceinline__ void ldsm_x4(uint32_t& r0, uint32_t& r1,
                                        uint32_t& r2, uint32_t& r3,
                                        uint32_t addr) {
    asm volatile("ldmatrix.sync.aligned.m8n8.x4.shared.b16 {%0,%1,%2,%3}, [%4];"
                 : "=r"(r0), "=r"(r1), "=r"(r2), "=r"(r3) : "r"(addr));
}
__device__ __forceinline__ void ldsm_x2(uint32_t& r0, uint32_t& r1,
                                        uint32_t addr) {
    asm volatile("ldmatrix.sync.aligned.m8n8.x2.shared.b16 {%0,%1}, [%2];"
                 : "=r"(r0), "=r"(r1) : "r"(addr));
}
__device__ __forceinline__ void mma16816(float& d0, float& d1, float& d2, float& d3,
                                         uint32_t a0, uint32_t a1, uint32_t a2,
                                         uint32_t a3, uint32_t b0, uint32_t b1) {
    asm volatile(
        "mma.sync.aligned.m16n8k16.row.col.f32.f16.f16.f32 "
        "{%0,%1,%2,%3}, {%4,%5,%6,%7}, {%8,%9}, {%0,%1,%2,%3};"
        : "+f"(d0), "+f"(d1), "+f"(d2), "+f"(d3)
        : "r"(a0), "r"(a1), "r"(a2), "r"(a3), "r"(b0), "r"(b1));
}

// ---------------- setup kernels --------------------------------------------
__global__ void zero_kernel() {
    int i = blockIdx.x * blockDim.x + threadIdx.x;
    if (i < N_NODES) g_degi[i] = 0;
    if (i < N_GRAPHS * D) g_gs[i] = 0.f;
    if (i < N_GRAPHS) g_gcnt[i] = 0.f;
}

// histogram + graph node counts in one pass
__global__ void hist_count_kernel(const int* __restrict__ col,
                                  const int* __restrict__ batch) {
    int i = blockIdx.x * blockDim.x + threadIdx.x;
    if (i < N_EDGES) atomicAdd(&g_degi[col[i]], 1);
    if (i < N_NODES) atomicAdd(&g_gcnt[batch[i]], 1.0f);
}

__global__ void scan_part_kernel() {
    __shared__ int wsum[32];
    int tid = threadIdx.x, lane = tid & 31, wid = tid >> 5;
    int idx = blockIdx.x * 1024 + tid;
    int v = (idx < N_NODES) ? g_degi[idx] : 0;
    if (idx < N_NODES) g_dinv[idx] = rsqrtf((float)(v + 1));
    int x = v;
    #pragma unroll
    for (int s = 1; s < 32; s <<= 1) {
        int t = __shfl_up_sync(0xffffffffu, x, s);
        if (lane >= s) x += t;
    }
    if (lane == 31) wsum[wid] = x;
    __syncthreads();
    if (wid == 0) {
        int y = wsum[lane];
        #pragma unroll
        for (int s = 1; s < 32; s <<= 1) {
            int t = __shfl_up_sync(0xffffffffu, y, s);
            if (lane >= s) y += t;
        }
        wsum[lane] = y;
    }
    __syncthreads();
    int incl = x + (wid ? wsum[wid - 1] : 0);
    if (idx < N_NODES) g_scan[idx] = incl;
    if (tid == 1023) g_bsum[blockIdx.x] = incl;
}

__global__ void scan_bsum_kernel() {
    int lane = threadIdx.x;
    int x0 = (lane < SCAN_BLKS) ? g_bsum[lane] : 0;
    int x1 = (lane + 32 < SCAN_BLKS) ? g_bsum[lane + 32] : 0;
    int i0 = x0;
    #pragma unroll
    for (int s = 1; s < 32; s <<= 1) {
        int t = __shfl_up_sync(0xffffffffu, i0, s);
        if (lane >= s) i0 += t;
    }
    int tot0 = __shfl_sync(0xffffffffu, i0, 31);
    int i1 = x1;
    #pragma unroll
    for (int s = 1; s < 32; s <<= 1) {
        int t = __shfl_up_sync(0xffffffffu, i1, s);
        if (lane >= s) i1 += t;
    }
    if (lane < SCAN_BLKS) g_boff[lane] = i0 - x0;
    if (lane + 32 < SCAN_BLKS) g_boff[lane + 32] = tot0 + i1 - x1;
}

__global__ void scan_final_kernel() {
    int idx = blockIdx.x * blockDim.x + threadIdx.x;
    if (idx == 0) g_rowptr[0] = 0;
    if (idx < N_NODES) {
        int incl = g_scan[idx] + g_boff[idx >> 10];
        g_rowptr[idx + 1] = incl;
        g_cursor[idx]     = incl - g_degi[idx];
    }
}

__global__ void scatter_kernel(const int* __restrict__ row,
                               const int* __restrict__ col) {
    int e = blockIdx.x * blockDim.x + threadIdx.x;
    if (e < N_EDGES) {
        int c = col[e];
        int p = atomicAdd(&g_cursor[c], 1);
        g_csr[p] = row[e];
    }
}

// convert x -> fp16 AND transpose+convert all 3 weight matrices, one kernel
__global__ void conv_kernel(const float* __restrict__ x,
                            const float* __restrict__ W1,
                            const float* __restrict__ W2,
                            const float* __restrict__ W3) {
    int i = blockIdx.x * blockDim.x + threadIdx.x;
    if (i < N_NODES * (D / 4)) {
        float4 v = ((const float4*)x)[i];
        uint2 o;
        o.x = hpack(v.x, v.y);
        o.y = hpack(v.z, v.w);
        ((uint2*)g_xb)[i] = o;
    }
    if (i < 3 * D * D) {
        int l = i >> 14;
        int r = i & (D * D - 1);
        int k = r >> 7, n = r & 127;
        const float* W = (l == 0) ? W1 : ((l == 1) ? W2 : W3);
        g_wt[l * D * D + n * D + k] = __float2half(W[k * D + n]);
    }
}

// ---------------- HMMA GEMM: out[m] = fp16( dinv[m] * (in[m] @ W) ) --------
// 256 threads (8 warps). Each warp: 16 M-rows x full N=128.
#define SM_STRIDE 136                       // fp16 elems per padded row
#define SM_ROWB   (SM_STRIDE * 2)           // 272 bytes
#define SM_A_OFF  0
#define SM_B_OFF  (128 * SM_ROWB)           // 34816
#define SM_TOT    (2 * 128 * SM_ROWB)       // 69632

__global__ void __launch_bounds__(256, 2)
mma_gemm_kernel(const __half* __restrict__ in,
                const __half* __restrict__ Wt,
                __half* __restrict__ out, int n) {
    extern __shared__ char smem[];
    uint32_t sb = smem_u32(smem);
    int tid = threadIdx.x, wid = tid >> 5, lane = tid & 31;
    int row0 = blockIdx.x * 128;

    const uint4* Ain = (const uint4*)(in + (size_t)row0 * D);
    const uint4* Bin = (const uint4*)Wt;
    #pragma unroll 4
    for (int i = tid; i < 2048; i += 256) {
        int r = i >> 4, g = i & 15;
        uint4 va = make_uint4(0u, 0u, 0u, 0u);
        if (row0 + r < n) va = Ain[i];
        *(uint4*)(smem + SM_A_OFF + r * SM_ROWB + g * 16) = va;
        *(uint4*)(smem + SM_B_OFF + r * SM_ROWB + g * 16) = Bin[i];
    }
    __syncthreads();

    int m_base = wid * 16;
    uint32_t a_addr = sb + SM_A_OFF
                    + (uint32_t)(m_base + (lane & 15)) * SM_ROWB
                    + (uint32_t)(lane >> 4) * 16;
    uint32_t b_addr = sb + SM_B_OFF
                    + (uint32_t)(lane & 7) * SM_ROWB
                    + (uint32_t)((lane >> 3) & 1) * 16;

    float acc[16][4];
    #pragma unroll
    for (int j = 0; j < 16; j++)
        #pragma unroll
        for (int q = 0; q < 4; q++) acc[j][q] = 0.f;

    #pragma unroll
    for (int kk = 0; kk < 8; kk++) {
        uint32_t a0, a1, a2, a3;
        ldsm_x4(a0, a1, a2, a3, a_addr + kk * 32);
        #pragma unroll
        for (int j = 0; j < 16; j++) {
            uint32_t b0, b1;
            ldsm_x2(b0, b1, b_addr + (uint32_t)j * 8 * SM_ROWB + kk * 32);
            mma16816(acc[j][0], acc[j][1], acc[j][2], acc[j][3],
                     a0, a1, a2, a3, b0, b1);
        }
    }

    int quad = lane >> 2;
    int tcol = (lane & 3) * 2;
    int r0 = row0 + m_base + quad;
    int r1 = r0 + 8;
    float dv0 = (r0 < n) ? g_dinv[r0] : 0.f;
    float dv1 = (r1 < n) ? g_dinv[r1] : 0.f;
    unsigned* o0 = (unsigned*)(out + (size_t)(r0 < n ? r0 : 0) * D);
    unsigned* o1 = (unsigned*)(out + (size_t)(r1 < n ? r1 : 0) * D);
    #pragma unroll
    for (int j = 0; j < 16; j++) {
        int nc = j * 8 + tcol;
        if (r0 < n) o0[nc >> 1] = hpack(acc[j][0] * dv0, acc[j][1] * dv0);
        if (r1 < n) o1[nc >> 1] = hpack(acc[j][2] * dv1, acc[j][3] * dv1);
    }
}

// ---------------- aggregation: warp per node, fp16 gather, fp32 acc --------
__global__ void agg_kernel(const uint2* __restrict__ hw,
                           const float* __restrict__ bias,
                           uint2* __restrict__ out, int relu) {
    int gt = blockIdx.x * blockDim.x + threadIdx.x;
    int v = gt >> 5;
    int lane = gt & 31;
    if (v >= N_NODES) return;

    float4 acc = h2f4(hw[v * 32 + lane]);
    int s = g_rowptr[v], e = g_rowptr[v + 1];
    int i = s;
    for (; i + 8 <= e; i += 8) {
        int u0 = g_csr[i],     u1 = g_csr[i + 1];
        int u2 = g_csr[i + 2], u3 = g_csr[i + 3];
        int u4 = g_csr[i + 4], u5 = g_csr[i + 5];
        int u6 = g_csr[i + 6], u7 = g_csr[i + 7];
        uint2 p0 = hw[u0 * 32 + lane];
        uint2 p1 = hw[u1 * 32 + lane];
        uint2 p2 = hw[u2 * 32 + lane];
        uint2 p3 = hw[u3 * 32 + lane];
        uint2 p4 = hw[u4 * 32 + lane];
        uint2 p5 = hw[u5 * 32 + lane];
        uint2 p6 = hw[u6 * 32 + lane];
        uint2 p7 = hw[u7 * 32 + lane];
        acc4(acc, h2f4(p0)); acc4(acc, h2f4(p1));
        acc4(acc, h2f4(p2)); acc4(acc, h2f4(p3));
        acc4(acc, h2f4(p4)); acc4(acc, h2f4(p5));
        acc4(acc, h2f4(p6)); acc4(acc, h2f4(p7));
    }
    for (; i + 2 <= e; i += 2) {
        int u0 = g_csr[i], u1 = g_csr[i + 1];
        uint2 p0 = hw[u0 * 32 + lane];
        uint2 p1 = hw[u1 * 32 + lane];
        acc4(acc, h2f4(p0)); acc4(acc, h2f4(p1));
    }
    if (i < e) acc4(acc, h2f4(hw[g_csr[i] * 32 + lane]));

    float dv = g_dinv[v];
    float4 b = ((const float4*)bias)[lane];
    float4 r;
    r.x = fmaf(dv, acc.x, b.x); r.y = fmaf(dv, acc.y, b.y);
    r.z = fmaf(dv, acc.z, b.z); r.w = fmaf(dv, acc.w, b.w);
    if (relu) {
        r.x = fmaxf(r.x, 0.f); r.y = fmaxf(r.y, 0.f);
        r.z = fmaxf(r.z, 0.f); r.w = fmaxf(r.w, 0.f);
    }
    out[v * 32 + lane] = make_uint2(hpack(r.x, r.y), hpack(r.z, r.w));
}

__global__ void agg_pool_kernel(const uint2* __restrict__ hw,
                                const float* __restrict__ bias,
                                const int* __restrict__ batch) {
    int gt = blockIdx.x * blockDim.x + threadIdx.x;
    int v = gt >> 5;
    int lane = gt & 31;
    if (v >= N_NODES) return;

    float4 acc = h2f4(hw[v * 32 + lane]);
    int s = g_rowptr[v], e = g_rowptr[v + 1];
    int i = s;
    for (; i + 8 <= e; i += 8) {
        int u0 = g_csr[i],     u1 = g_csr[i + 1];
        int u2 = g_csr[i + 2], u3 = g_csr[i + 3];
        int u4 = g_csr[i + 4], u5 = g_csr[i + 5];
        int u6 = g_csr[i + 6], u7 = g_csr[i + 7];
        uint2 p0 = hw[u0 * 32 + lane];
        uint2 p1 = hw[u1 * 32 + lane];
        uint2 p2 = hw[u2 * 32 + lane];
        uint2 p3 = hw[u3 * 32 + lane];
        uint2 p4 = hw[u4 * 32 + lane];
        uint2 p5 = hw[u5 * 32 + lane];
        uint2 p6 = hw[u6 * 32 + lane];
        uint2 p7 = hw[u7 * 32 + lane];
        acc4(acc, h2f4(p0)); acc4(acc, h2f4(p1));
        acc4(acc, h2f4(p2)); acc4(acc, h2f4(p3));
        acc4(acc, h2f4(p4)); acc4(acc, h2f4(p5));
        acc4(acc, h2f4(p6)); acc4(acc, h2f4(p7));
    }
    for (; i + 2 <= e; i += 2) {
        int u0 = g_csr[i], u1 = g_csr[i + 1];
        uint2 p0 = hw[u0 * 32 + lane];
        uint2 p1 = hw[u1 * 32 + lane];
        acc4(acc, h2f4(p0)); acc4(acc, h2f4(p1));
    }
    if (i < e) acc4(acc, h2f4(hw[g_csr[i] * 32 + lane]));

    float dv = g_dinv[v];
    float4 b = ((const float4*)bias)[lane];
    float4 r;
    r.x = fmaf(dv, acc.x, b.x); r.y = fmaf(dv, acc.y, b.y);
    r.z = fmaf(dv, acc.z, b.z); r.w = fmaf(dv, acc.w, b.w);

    int g = batch[v];
    float* base = &g_gs[g * D + lane * 4];
    atomicAdd(base + 0, r.x);
    atomicAdd(base + 1, r.y);
    atomicAdd(base + 2, r.z);
    atomicAdd(base + 3, r.w);
}

__global__ void final_kernel(const float* __restrict__ Wlin,
                             const float* __restrict__ blin,
                             float* __restrict__ out) {
    __shared__ float Ws[D * 3];
    int t = threadIdx.x;
    for (int i = t; i < D * 3; i += 128) Ws[i] = Wlin[i];
    __syncthreads();
    int g = t;
    float inv = 1.0f / fmaxf(g_gcnt[g], 1.0f);
    float o0 = blin[0], o1 = blin[1], o2 = blin[2];
    #pragma unroll 4
    for (int c = 0; c < D; ++c) {
        float p = g_gs[g * D + c] * inv;
        o0 = fmaf(p, Ws[c * 3 + 0], o0);
        o1 = fmaf(p, Ws[c * 3 + 1], o1);
        o2 = fmaf(p, Ws[c * 3 + 2], o2);
    }
    out[g * 3 + 0] = o0;
    out[g * 3 + 1] = o1;
    out[g * 3 + 2] = o2;
}

// ---------------- launch ----------------------------------------------------
extern "C" void kernel_launch(void* const* d_in, const int* in_sizes, int n_in,
                              void* d_out, int out_size) {
    const float* x     = (const float*)d_in[0];
    const int*   ei    = (const int*)d_in[1];
    const int*   batch = (const int*)d_in[2];
    const float* W1 = (const float*)d_in[3];
    const float* b1 = (const float*)d_in[4];
    const float* W2 = (const float*)d_in[5];
    const float* b2 = (const float*)d_in[6];
    const float* W3 = (const float*)d_in[7];
    const float* b3 = (const float*)d_in[8];
    const float* Wlin = (const float*)d_in[9];
    const float* blin = (const float*)d_in[10];
    float* out = (float*)d_out;

    const int* row = ei;
    const int* col = ei + N_EDGES;

    cudaFuncSetAttribute(mma_gemm_kernel,
                         cudaFuncAttributeMaxDynamicSharedMemorySize, SM_TOT);

    __half *xb_p = nullptr, *hw_p = nullptr, *hb_p = nullptr, *wt_p = nullptr;
    cudaGetSymbolAddress((void**)&xb_p, g_xb);
    cudaGetSymbolAddress((void**)&hw_p, g_hw);
    cudaGetSymbolAddress((void**)&hb_p, g_hb);
    cudaGetSymbolAddress((void**)&wt_p, g_wt);

    const int nodeBlocks = (N_NODES + 255) / 256;
    const int edgeBlocks = (N_EDGES + 255) / 256;
    const int gemmGrid   = (N_NODES + 127) / 128;
    const int aggBlocks  = (N_NODES * 32 + 255) / 256;
    const int convBlocks = (N_NODES * 32 + 255) / 256;

    zero_kernel<<<nodeBlocks, 256>>>();
    hist_count_kernel<<<edgeBlocks, 256>>>(col, batch);
    scan_part_kernel<<<SCAN_BLKS, 1024>>>();
    scan_bsum_kernel<<<1, 32>>>();
    scan_final_kernel<<<(N_NODES + 1023) / 1024, 1024>>>();
    scatter_kernel<<<edgeBlocks, 256>>>(row, col);
    conv_kernel<<<convBlocks, 256>>>(x, W1, W2, W3);

    // layer 1
    mma_gemm_kernel<<<gemmGrid, 256, SM_TOT>>>(xb_p, wt_p, hw_p, N_NODES);
    agg_kernel<<<aggBlocks, 256>>>((const uint2*)hw_p, b1, (uint2*)hb_p, 1);
    // layer 2
    mma_gemm_kernel<<<gemmGrid, 256, SM_TOT>>>(hb_p, wt_p + D * D, hw_p, N_NODES);
    agg_kernel<<<aggBlocks, 256>>>((const uint2*)hw_p, b2, (uint2*)hb_p, 1);
    // layer 3 (fused pooling)
    mma_gemm_kernel<<<gemmGrid, 256, SM_TOT>>>(hb_p, wt_p + 2 * D * D, hw_p, N_NODES);
    agg_pool_kernel<<<aggBlocks, 256>>>((const uint2*)hw_p, b3, batch);

    final_kernel<<<1, 128>>>(Wlin, blin, out);
}